// round 3
// baseline (speedup 1.0000x reference)
#include <cuda_runtime.h>
#include <cuda_bf16.h>

// Problem constants (fixed by the dataset)
constexpr int NN  = 10000;   // nodes
constexpr int NE  = 640000;  // edges
constexpr int C_IN  = 128;
constexpr int C_HID = 128;
constexpr int C_OUT = 64;

// Scratch (device globals — no allocation allowed)
__device__ __align__(256) float g_deg [NN];
__device__ __align__(256) float g_dinv[NN];
__device__ __align__(256) float g_norm[NE];
__device__ __align__(256) float g_xw  [NN * C_HID];   // x @ W1
__device__ __align__(256) float g_h   [NN * C_HID];   // hidden after agg+bias(+relu)
__device__ __align__(256) float g_hw  [NN * C_OUT];   // h @ W2

// edge_index dtype detection: 0 -> int32, 1 -> int64 (little-endian)
__device__ int g_odd_nonzero;

__global__ void k_detect_init() {
    if (threadIdx.x == 0 && blockIdx.x == 0) g_odd_nonzero = 0;
}

__global__ void k_detect(const int* __restrict__ ei32) {
    int i = blockIdx.x * blockDim.x + threadIdx.x;
    if (i < 2048) {
        if (ei32[2 * i + 1] != 0) atomicOr(&g_odd_nonzero, 1);
    }
}

// load edge index at logical position pos (0..2*NE-1); is64 uniform per launch
__device__ __forceinline__ int load_idx(const int* __restrict__ ei32, long pos) {
    // int64 little-endian: value's low word at 2*pos. int32: at pos.
    return (g_odd_nonzero == 0) ? ei32[2 * pos] : ei32[pos];
}

// ---------------------------------------------------------------------------
// degree / norm
// ---------------------------------------------------------------------------
__global__ void k_init_deg() {
    int i = blockIdx.x * blockDim.x + threadIdx.x;
    if (i < NN) g_deg[i] = 1.0f;  // self-loop weight
}

__global__ void k_deg(const int* __restrict__ ei32,
                      const float* __restrict__ w) {
    int e = blockIdx.x * blockDim.x + threadIdx.x;
    if (e < NE) {
        int dst = load_idx(ei32, (long)NE + e);
        if (dst >= 0 && dst < NN) atomicAdd(&g_deg[dst], w[e]);
    }
}

__global__ void k_dinv() {
    int i = blockIdx.x * blockDim.x + threadIdx.x;
    if (i < NN) {
        float d = g_deg[i];
        g_dinv[i] = (d > 0.0f) ? rsqrtf(d) : 0.0f;
    }
}

__global__ void k_norm(const int* __restrict__ ei32,
                       const float* __restrict__ w) {
    int e = blockIdx.x * blockDim.x + threadIdx.x;
    if (e < NE) {
        int s = load_idx(ei32, e);
        int d = load_idx(ei32, (long)NE + e);
        float nv = 0.0f;
        if (s >= 0 && s < NN && d >= 0 && d < NN)
            nv = g_dinv[s] * w[e] * g_dinv[d];
        g_norm[e] = nv;
    }
}

// ---------------------------------------------------------------------------
// fp32 tiled GEMM body:  C[M,N] = A[M,K] @ B[K,N]  (blockDim = 256)
// ---------------------------------------------------------------------------
__device__ __forceinline__ void gemm_body(const float* __restrict__ A,
                                          const float* __restrict__ B,
                                          float* __restrict__ C,
                                          int M, int N, int K) {
    constexpr int BM = 64, BN = 64, BK = 16;
    __shared__ float As[BK][BM];
    __shared__ float Bs[BK][BN];

    int rowBase = blockIdx.x * BM;
    int colBase = blockIdx.y * BN;
    int tx = threadIdx.x % 16;
    int ty = threadIdx.x / 16;

    float acc[4][4];
#pragma unroll
    for (int m = 0; m < 4; m++)
#pragma unroll
        for (int n = 0; n < 4; n++) acc[m][n] = 0.0f;

    for (int k0 = 0; k0 < K; k0 += BK) {
        for (int i = threadIdx.x; i < BM * BK; i += 256) {
            int r = i / BK, c = i % BK;
            int gr = rowBase + r;
            As[c][r] = (gr < M) ? A[(long)gr * K + k0 + c] : 0.0f;
        }
        for (int i = threadIdx.x; i < BK * BN; i += 256) {
            int r = i / BN, c = i % BN;
            Bs[r][c] = B[(long)(k0 + r) * N + colBase + c];
        }
        __syncthreads();

#pragma unroll
        for (int k = 0; k < BK; k++) {
            float a[4], b[4];
#pragma unroll
            for (int m = 0; m < 4; m++) a[m] = As[k][ty * 4 + m];
#pragma unroll
            for (int n = 0; n < 4; n++) b[n] = Bs[k][tx * 4 + n];
#pragma unroll
            for (int m = 0; m < 4; m++)
#pragma unroll
                for (int n = 0; n < 4; n++) acc[m][n] += a[m] * b[n];
        }
        __syncthreads();
    }

#pragma unroll
    for (int m = 0; m < 4; m++) {
        int gr = rowBase + ty * 4 + m;
        if (gr < M) {
#pragma unroll
            for (int n = 0; n < 4; n++)
                C[(long)gr * N + colBase + tx * 4 + n] = acc[m][n];
        }
    }
}

__global__ void k_gemm1(const float* __restrict__ x,
                        const float* __restrict__ W1) {
    gemm_body(x, W1, g_xw, NN, C_HID, C_IN);
}

__global__ void k_gemm2(const float* __restrict__ W2) {
    gemm_body(g_h, W2, g_hw, NN, C_OUT, C_HID);
}

// ---------------------------------------------------------------------------
// self-loop init (+ bias):  out[i,c] = dinv[i]^2 * xw[i,c] + bias[c]
// ---------------------------------------------------------------------------
__global__ void k_selfinit1(const float* __restrict__ bias) {
    int idx = blockIdx.x * blockDim.x + threadIdx.x;
    if (idx < NN * C_HID) {
        int i = idx >> 7;
        int c = idx & (C_HID - 1);
        float di = g_dinv[i];
        g_h[idx] = di * di * g_xw[idx] + bias[c];
    }
}

__global__ void k_selfinit2(const float* __restrict__ bias,
                            float* __restrict__ out) {
    int idx = blockIdx.x * blockDim.x + threadIdx.x;
    if (idx < NN * C_OUT) {
        int i = idx / C_OUT;
        int c = idx & (C_OUT - 1);
        float di = g_dinv[i];
        out[idx] = di * di * g_hw[idx] + bias[c];
    }
}

// ---------------------------------------------------------------------------
// edge scatter-add:  out[dst, :] += norm[e] * src_feat[src, :]
// one thread = one (edge, 4-channel chunk)
// ---------------------------------------------------------------------------
__global__ void k_scatter1(const int* __restrict__ ei32) {
    constexpr int CHUNKS = C_HID / 4;  // 32
    long gid = (long)blockIdx.x * blockDim.x + threadIdx.x;
    if (gid >= (long)NE * CHUNKS) return;
    int e  = (int)(gid >> 5);
    int ch = (int)(gid & (CHUNKS - 1));

    int s = load_idx(ei32, e);
    int d = load_idx(ei32, (long)NE + e);
    if ((unsigned)s >= (unsigned)NN || (unsigned)d >= (unsigned)NN) return;
    float nv = g_norm[e];

    float4 v = reinterpret_cast<const float4*>(g_xw + (long)s * C_HID)[ch];
    float* o = g_h + (long)d * C_HID + ch * 4;
    atomicAdd(o + 0, nv * v.x);
    atomicAdd(o + 1, nv * v.y);
    atomicAdd(o + 2, nv * v.z);
    atomicAdd(o + 3, nv * v.w);
}

__global__ void k_scatter2(const int* __restrict__ ei32,
                           float* __restrict__ out) {
    constexpr int CHUNKS = C_OUT / 4;  // 16
    long gid = (long)blockIdx.x * blockDim.x + threadIdx.x;
    if (gid >= (long)NE * CHUNKS) return;
    int e  = (int)(gid >> 4);
    int ch = (int)(gid & (CHUNKS - 1));

    int s = load_idx(ei32, e);
    int d = load_idx(ei32, (long)NE + e);
    if ((unsigned)s >= (unsigned)NN || (unsigned)d >= (unsigned)NN) return;
    float nv = g_norm[e];

    float4 v = reinterpret_cast<const float4*>(g_hw + (long)s * C_OUT)[ch];
    float* o = out + (long)d * C_OUT + ch * 4;
    atomicAdd(o + 0, nv * v.x);
    atomicAdd(o + 1, nv * v.y);
    atomicAdd(o + 2, nv * v.z);
    atomicAdd(o + 3, nv * v.w);
}

__global__ void k_relu() {
    int idx = blockIdx.x * blockDim.x + threadIdx.x;
    if (idx < NN * C_HID) g_h[idx] = fmaxf(g_h[idx], 0.0f);
}

// ---------------------------------------------------------------------------
// launch
// ---------------------------------------------------------------------------
extern "C" void kernel_launch(void* const* d_in, const int* in_sizes, int n_in,
                              void* d_out, int out_size) {
    const float* x    = (const float*)d_in[0];
    const int*   ei32 = (const int*)d_in[1];
    const float* w    = (const float*)d_in[2];
    const float* W1   = (const float*)d_in[3];
    const float* b1   = (const float*)d_in[4];
    const float* W2   = (const float*)d_in[5];
    const float* b2   = (const float*)d_in[6];
    float* out = (float*)d_out;

    const int T = 256;

    // dtype detection for edge_index (int32 vs int64)
    k_detect_init<<<1, 32>>>();
    k_detect<<<(2048 + T - 1) / T, T>>>(ei32);

    // degree / norm (shared by both layers)
    k_init_deg<<<(NN + T - 1) / T, T>>>();
    k_deg<<<(NE + T - 1) / T, T>>>(ei32, w);
    k_dinv<<<(NN + T - 1) / T, T>>>();
    k_norm<<<(NE + T - 1) / T, T>>>(ei32, w);

    // layer 1
    {
        dim3 grid((NN + 63) / 64, C_HID / 64);
        k_gemm1<<<grid, 256>>>(x, W1);
    }
    k_selfinit1<<<(NN * C_HID + T - 1) / T, T>>>(b1);
    {
        long total = (long)NE * (C_HID / 4);
        k_scatter1<<<(int)((total + T - 1) / T), T>>>(ei32);
    }
    k_relu<<<(NN * C_HID + T - 1) / T, T>>>();

    // layer 2
    {
        dim3 grid((NN + 63) / 64, C_OUT / 64);
        k_gemm2<<<grid, 256>>>(W2);
    }
    k_selfinit2<<<(NN * C_OUT + T - 1) / T, T>>>(b2, out);
    {
        long total = (long)NE * (C_OUT / 4);
        k_scatter2<<<(int)((total + T - 1) / T), T>>>(ei32, out);
    }
}

// round 4
// speedup vs baseline: 2.4811x; 2.4811x over previous
#include <cuda_runtime.h>
#include <cuda_bf16.h>

constexpr int NN  = 10000;
constexpr int NE  = 640000;
constexpr int C_IN  = 128;
constexpr int C_HID = 128;
constexpr int C_OUT = 64;

struct __align__(8) Edge { int s; float c; };

// Scratch (device globals — no allocation allowed)
__device__ __align__(256) float g_deg [NN];
__device__ __align__(256) float g_dinv[NN];
__device__ __align__(256) int   g_count[NN];
__device__ __align__(256) int   g_rowptr[NN + 1];
__device__ __align__(256) int   g_cursor[NN];
__device__ __align__(256) Edge  g_csr [NE];
__device__ __align__(256) float g_xw  [NN * C_HID];
__device__ __align__(256) float g_h   [NN * C_HID];
__device__ __align__(256) float g_hw  [NN * C_OUT];

// edge_index dtype detection: 0 -> int64 (odd words all zero), 1 -> int32
__device__ int g_odd_nonzero;

__global__ void k_detect_init() {
    if (threadIdx.x == 0 && blockIdx.x == 0) g_odd_nonzero = 0;
}
__global__ void k_detect(const int* __restrict__ ei32) {
    int i = blockIdx.x * blockDim.x + threadIdx.x;
    if (i < 2048) {
        if (ei32[2 * i + 1] != 0) atomicOr(&g_odd_nonzero, 1);
    }
}
__device__ __forceinline__ int load_idx(const int* __restrict__ ei32, long pos) {
    return (g_odd_nonzero == 0) ? ei32[2 * pos] : ei32[pos];
}

// ---------------------------------------------------------------------------
// CSR build + degree
// ---------------------------------------------------------------------------
__global__ void k_zero() {
    int i = blockIdx.x * blockDim.x + threadIdx.x;
    if (i < NN) { g_deg[i] = 1.0f; g_count[i] = 0; }
}

__global__ void k_count_deg(const int* __restrict__ ei32,
                            const float* __restrict__ w) {
    int e = blockIdx.x * blockDim.x + threadIdx.x;
    if (e < NE) {
        int dst = load_idx(ei32, (long)NE + e);
        if ((unsigned)dst < (unsigned)NN) {
            atomicAdd(&g_count[dst], 1);
            atomicAdd(&g_deg[dst], w[e]);
        }
    }
}

__global__ void k_dinv() {
    int i = blockIdx.x * blockDim.x + threadIdx.x;
    if (i < NN) {
        float d = g_deg[i];
        g_dinv[i] = (d > 0.0f) ? rsqrtf(d) : 0.0f;
    }
}

// single-block exclusive scan of g_count -> g_rowptr / g_cursor (1024 thr)
__global__ void k_scan() {
    constexpr int T = 1024, ITEMS = 10;  // 1024*10 >= 10000
    __shared__ int partials[T];
    int t = threadIdx.x;
    int base = t * ITEMS;
    int local[ITEMS];
    int sum = 0;
#pragma unroll
    for (int i = 0; i < ITEMS; i++) {
        int idx = base + i;
        int v = (idx < NN) ? g_count[idx] : 0;
        local[i] = sum;
        sum += v;
    }
    partials[t] = sum;
    __syncthreads();
    // inclusive scan of partials
    for (int off = 1; off < T; off <<= 1) {
        int v = (t >= off) ? partials[t - off] : 0;
        __syncthreads();
        partials[t] += v;
        __syncthreads();
    }
    int prev = (t == 0) ? 0 : partials[t - 1];
#pragma unroll
    for (int i = 0; i < ITEMS; i++) {
        int idx = base + i;
        if (idx < NN) {
            int off = prev + local[i];
            g_rowptr[idx] = off;
            g_cursor[idx] = off;
        }
    }
    if (t == T - 1) g_rowptr[NN] = partials[T - 1];
}

__global__ void k_fill(const int* __restrict__ ei32,
                       const float* __restrict__ w) {
    int e = blockIdx.x * blockDim.x + threadIdx.x;
    if (e < NE) {
        int s = load_idx(ei32, e);
        int d = load_idx(ei32, (long)NE + e);
        if ((unsigned)s >= (unsigned)NN || (unsigned)d >= (unsigned)NN) return;
        float coef = g_dinv[s] * w[e] * g_dinv[d];
        int pos = atomicAdd(&g_cursor[d], 1);
        Edge ed; ed.s = s; ed.c = coef;
        g_csr[pos] = ed;
    }
}

// ---------------------------------------------------------------------------
// fp32 tiled GEMM body:  C[M,N] = A[M,K] @ B[K,N]  (blockDim = 256)
// ---------------------------------------------------------------------------
__device__ __forceinline__ void gemm_body(const float* __restrict__ A,
                                          const float* __restrict__ B,
                                          float* __restrict__ C,
                                          int M, int N, int K) {
    constexpr int BM = 64, BN = 64, BK = 16;
    __shared__ float As[BK][BM];
    __shared__ float Bs[BK][BN];

    int rowBase = blockIdx.x * BM;
    int colBase = blockIdx.y * BN;
    int tx = threadIdx.x % 16;
    int ty = threadIdx.x / 16;

    float acc[4][4];
#pragma unroll
    for (int m = 0; m < 4; m++)
#pragma unroll
        for (int n = 0; n < 4; n++) acc[m][n] = 0.0f;

    for (int k0 = 0; k0 < K; k0 += BK) {
        for (int i = threadIdx.x; i < BM * BK; i += 256) {
            int r = i / BK, c = i % BK;
            int gr = rowBase + r;
            As[c][r] = (gr < M) ? A[(long)gr * K + k0 + c] : 0.0f;
        }
        for (int i = threadIdx.x; i < BK * BN; i += 256) {
            int r = i / BN, c = i % BN;
            Bs[r][c] = B[(long)(k0 + r) * N + colBase + c];
        }
        __syncthreads();

#pragma unroll
        for (int k = 0; k < BK; k++) {
            float a[4], b[4];
#pragma unroll
            for (int m = 0; m < 4; m++) a[m] = As[k][ty * 4 + m];
#pragma unroll
            for (int n = 0; n < 4; n++) b[n] = Bs[k][tx * 4 + n];
#pragma unroll
            for (int m = 0; m < 4; m++)
#pragma unroll
                for (int n = 0; n < 4; n++) acc[m][n] += a[m] * b[n];
        }
        __syncthreads();
    }

#pragma unroll
    for (int m = 0; m < 4; m++) {
        int gr = rowBase + ty * 4 + m;
        if (gr < M) {
#pragma unroll
            for (int n = 0; n < 4; n++)
                C[(long)gr * N + colBase + tx * 4 + n] = acc[m][n];
        }
    }
}

__global__ void k_gemm1(const float* __restrict__ x,
                        const float* __restrict__ W1) {
    gemm_body(x, W1, g_xw, NN, C_HID, C_IN);
}
__global__ void k_gemm2(const float* __restrict__ W2) {
    gemm_body(g_h, W2, g_hw, NN, C_OUT, C_HID);
}

// ---------------------------------------------------------------------------
// fused gather-aggregate:  out[i,:] = f( dinv^2*xw[i,:] + b + sum coef*xw[s,:] )
// one block per node, one thread per channel
// ---------------------------------------------------------------------------
__global__ void __launch_bounds__(C_HID) k_agg1(const float* __restrict__ b1) {
    int node = blockIdx.x;
    int c = threadIdx.x;
    __shared__ Edge tile[C_HID];

    float di = g_dinv[node];
    float acc = di * di * g_xw[node * C_HID + c] + b1[c];

    int beg = g_rowptr[node];
    int end = g_rowptr[node + 1];
    for (int t = beg; t < end; t += C_HID) {
        int n = min(C_HID, end - t);
        if (c < n) tile[c] = g_csr[t + c];
        __syncthreads();
        int j = 0;
        for (; j + 4 <= n; j += 4) {
            Edge e0 = tile[j], e1 = tile[j + 1], e2 = tile[j + 2], e3 = tile[j + 3];
            float v0 = g_xw[e0.s * C_HID + c];
            float v1 = g_xw[e1.s * C_HID + c];
            float v2 = g_xw[e2.s * C_HID + c];
            float v3 = g_xw[e3.s * C_HID + c];
            acc += e0.c * v0; acc += e1.c * v1; acc += e2.c * v2; acc += e3.c * v3;
        }
        for (; j < n; j++) {
            Edge e = tile[j];
            acc += e.c * g_xw[e.s * C_HID + c];
        }
        __syncthreads();
    }
    g_h[node * C_HID + c] = fmaxf(acc, 0.0f);
}

__global__ void __launch_bounds__(C_OUT) k_agg2(const float* __restrict__ b2,
                                                float* __restrict__ out) {
    int node = blockIdx.x;
    int c = threadIdx.x;
    __shared__ Edge tile[C_OUT];

    float di = g_dinv[node];
    float acc = di * di * g_hw[node * C_OUT + c] + b2[c];

    int beg = g_rowptr[node];
    int end = g_rowptr[node + 1];
    for (int t = beg; t < end; t += C_OUT) {
        int n = min(C_OUT, end - t);
        if (c < n) tile[c] = g_csr[t + c];
        __syncthreads();
        int j = 0;
        for (; j + 4 <= n; j += 4) {
            Edge e0 = tile[j], e1 = tile[j + 1], e2 = tile[j + 2], e3 = tile[j + 3];
            float v0 = g_hw[e0.s * C_OUT + c];
            float v1 = g_hw[e1.s * C_OUT + c];
            float v2 = g_hw[e2.s * C_OUT + c];
            float v3 = g_hw[e3.s * C_OUT + c];
            acc += e0.c * v0; acc += e1.c * v1; acc += e2.c * v2; acc += e3.c * v3;
        }
        for (; j < n; j++) {
            Edge e = tile[j];
            acc += e.c * g_hw[e.s * C_OUT + c];
        }
        __syncthreads();
    }
    out[node * C_OUT + c] = acc;
}

// ---------------------------------------------------------------------------
// launch
// ---------------------------------------------------------------------------
extern "C" void kernel_launch(void* const* d_in, const int* in_sizes, int n_in,
                              void* d_out, int out_size) {
    const float* x    = (const float*)d_in[0];
    const int*   ei32 = (const int*)d_in[1];
    const float* w    = (const float*)d_in[2];
    const float* W1   = (const float*)d_in[3];
    const float* b1   = (const float*)d_in[4];
    const float* W2   = (const float*)d_in[5];
    const float* b2   = (const float*)d_in[6];
    float* out = (float*)d_out;

    const int T = 256;

    k_detect_init<<<1, 32>>>();
    k_detect<<<(2048 + T - 1) / T, T>>>(ei32);

    // CSR build + degrees (graph shared by both layers)
    k_zero<<<(NN + T - 1) / T, T>>>();
    k_count_deg<<<(NE + T - 1) / T, T>>>(ei32, w);
    k_dinv<<<(NN + T - 1) / T, T>>>();
    k_scan<<<1, 1024>>>();
    k_fill<<<(NE + T - 1) / T, T>>>(ei32, w);

    // layer 1: xw = x @ W1, then fused aggregate + self-loop + bias + relu
    {
        dim3 grid((NN + 63) / 64, C_HID / 64);
        k_gemm1<<<grid, 256>>>(x, W1);
    }
    k_agg1<<<NN, C_HID>>>(b1);

    // layer 2
    {
        dim3 grid((NN + 63) / 64, C_OUT / 64);
        k_gemm2<<<grid, 256>>>(W2);
    }
    k_agg2<<<NN, C_OUT>>>(b2, out);
}

// round 5
// speedup vs baseline: 2.7618x; 1.1132x over previous
#include <cuda_runtime.h>
#include <cuda_bf16.h>

constexpr int NN  = 10000;
constexpr int NE  = 640000;
constexpr int C_IN  = 128;
constexpr int C_HID = 128;
constexpr int C_OUT = 64;

struct __align__(8) Edge { int s; float c; };

// Scratch (device globals — no allocation allowed)
__device__ __align__(256) float g_dinv[NN];
__device__ __align__(256) int   g_count[NN];
__device__ __align__(256) int   g_rowptr[NN + 1];
__device__ __align__(256) int   g_sd  [NE];       // packed (s | d<<16)
__device__ __align__(256) int   g_rank[NE];
__device__ __align__(256) Edge  g_csr [NE];
__device__ __align__(256) float g_xs  [NN * C_HID];  // dinv * (x @ W1)
__device__ __align__(256) float g_h   [NN * C_HID];  // relu(layer1 out)
__device__ __align__(256) float g_hs  [NN * C_OUT];  // dinv * (h @ W2)

// edge_index dtype: 0 -> int64 (odd 32-bit words all zero), 1 -> int32.
// Zero-initialized at module load; atomicOr sets the same value every replay.
__device__ int g_odd_nonzero;

__device__ __forceinline__ int load_idx(const int* __restrict__ ei32, long pos) {
    return (g_odd_nonzero == 0) ? ei32[2 * pos] : ei32[pos];
}

// ---------------------------------------------------------------------------
// zero counters + detect dtype (one kernel)
// ---------------------------------------------------------------------------
__global__ void k_zero_detect(const int* __restrict__ ei32) {
    int i = blockIdx.x * blockDim.x + threadIdx.x;
    if (i < NN) g_count[i] = 0;
    if (i < 2048) {
        if (ei32[2 * i + 1] != 0) atomicOr(&g_odd_nonzero, 1);
    }
}

// ---------------------------------------------------------------------------
// count + rank + pack (1 atomic per edge)
// ---------------------------------------------------------------------------
__global__ void k_count(const int* __restrict__ ei32) {
    int e = blockIdx.x * blockDim.x + threadIdx.x;
    if (e < NE) {
        int s = load_idx(ei32, e);
        int d = load_idx(ei32, (long)NE + e);
        s = min(max(s, 0), NN - 1);
        d = min(max(d, 0), NN - 1);
        g_sd[e] = s | (d << 16);
        g_rank[e] = atomicAdd(&g_count[d], 1);
    }
}

// single-block exclusive scan of g_count -> g_rowptr (1024 thr)
__global__ void k_scan() {
    constexpr int T = 1024, ITEMS = 10;  // 1024*10 >= 10000
    __shared__ int partials[T];
    int t = threadIdx.x;
    int base = t * ITEMS;
    int local[ITEMS];
    int sum = 0;
#pragma unroll
    for (int i = 0; i < ITEMS; i++) {
        int idx = base + i;
        int v = (idx < NN) ? g_count[idx] : 0;
        local[i] = sum;
        sum += v;
    }
    partials[t] = sum;
    __syncthreads();
    for (int off = 1; off < T; off <<= 1) {
        int v = (t >= off) ? partials[t - off] : 0;
        __syncthreads();
        partials[t] += v;
        __syncthreads();
    }
    int prev = (t == 0) ? 0 : partials[t - 1];
#pragma unroll
    for (int i = 0; i < ITEMS; i++) {
        int idx = base + i;
        if (idx < NN) g_rowptr[idx] = prev + local[i];
    }
    if (t == T - 1) g_rowptr[NN] = partials[T - 1];
}

// fill CSR (no atomics): csr[rowptr[d] + rank[e]] = {s, w[e]}
__global__ void k_fill(const float* __restrict__ w) {
    int e = blockIdx.x * blockDim.x + threadIdx.x;
    if (e < NE) {
        int sd = g_sd[e];
        int s = sd & 0xFFFF;
        int d = sd >> 16;
        int pos = g_rowptr[d] + g_rank[e];
        Edge ed; ed.s = s; ed.c = w[e];
        g_csr[pos] = ed;
    }
}

// per-node weighted degree from CSR rows (coalesced), dinv = rsqrt(1 + sum w)
__global__ void k_dinv() {
    int gw = (blockIdx.x * blockDim.x + threadIdx.x) >> 5;
    int lane = threadIdx.x & 31;
    if (gw >= NN) return;
    int beg = g_rowptr[gw], end = g_rowptr[gw + 1];
    float sum = 0.0f;
    for (int i = beg + lane; i < end; i += 32) sum += g_csr[i].c;
#pragma unroll
    for (int off = 16; off > 0; off >>= 1)
        sum += __shfl_down_sync(0xFFFFFFFF, sum, off);
    if (lane == 0) g_dinv[gw] = rsqrtf(1.0f + sum);
}

// ---------------------------------------------------------------------------
// fp32 tiled GEMM, epilogue scales row by dinv[row]:  C = diag(dinv) * (A @ B)
// ---------------------------------------------------------------------------
__device__ __forceinline__ void gemm_body(const float* __restrict__ A,
                                          const float* __restrict__ B,
                                          float* __restrict__ C,
                                          int M, int N, int K) {
    constexpr int BM = 64, BN = 64, BK = 16;
    __shared__ float As[BK][BM];
    __shared__ float Bs[BK][BN];

    int rowBase = blockIdx.x * BM;
    int colBase = blockIdx.y * BN;
    int tx = threadIdx.x % 16;
    int ty = threadIdx.x / 16;

    float acc[4][4];
#pragma unroll
    for (int m = 0; m < 4; m++)
#pragma unroll
        for (int n = 0; n < 4; n++) acc[m][n] = 0.0f;

    for (int k0 = 0; k0 < K; k0 += BK) {
        for (int i = threadIdx.x; i < BM * BK; i += 256) {
            int r = i / BK, c = i % BK;
            int gr = rowBase + r;
            As[c][r] = (gr < M) ? A[(long)gr * K + k0 + c] : 0.0f;
        }
        for (int i = threadIdx.x; i < BK * BN; i += 256) {
            int r = i / BN, c = i % BN;
            Bs[r][c] = B[(long)(k0 + r) * N + colBase + c];
        }
        __syncthreads();

#pragma unroll
        for (int k = 0; k < BK; k++) {
            float a[4], b[4];
#pragma unroll
            for (int m = 0; m < 4; m++) a[m] = As[k][ty * 4 + m];
#pragma unroll
            for (int n = 0; n < 4; n++) b[n] = Bs[k][tx * 4 + n];
#pragma unroll
            for (int m = 0; m < 4; m++)
#pragma unroll
                for (int n = 0; n < 4; n++) acc[m][n] += a[m] * b[n];
        }
        __syncthreads();
    }

#pragma unroll
    for (int m = 0; m < 4; m++) {
        int gr = rowBase + ty * 4 + m;
        if (gr < M) {
            float di = g_dinv[gr];
#pragma unroll
            for (int n = 0; n < 4; n++)
                C[(long)gr * N + colBase + tx * 4 + n] = di * acc[m][n];
        }
    }
}

__global__ void k_gemm1(const float* __restrict__ x,
                        const float* __restrict__ W1) {
    gemm_body(x, W1, g_xs, NN, C_HID, C_IN);
}
__global__ void k_gemm2(const float* __restrict__ W2) {
    gemm_body(g_h, W2, g_hs, NN, C_OUT, C_HID);
}

// ---------------------------------------------------------------------------
// warp-per-node gather-aggregate (float4 channels, shfl edge broadcast)
//   out[d,:] = relu( dinv[d] * ( xs[d,:] + sum_e w_e * xs[s_e,:] ) + b )
// ---------------------------------------------------------------------------
__global__ void __launch_bounds__(256) k_agg1(const float* __restrict__ b1) {
    int node = (blockIdx.x * blockDim.x + threadIdx.x) >> 5;
    int lane = threadIdx.x & 31;
    if (node >= NN) return;

    const float4* xs4 = reinterpret_cast<const float4*>(g_xs);
    float4 acc = xs4[node * 32 + lane];  // self term (already dinv-scaled)

    int beg = g_rowptr[node], end = g_rowptr[node + 1];
    for (int t = beg; t < end; t += 32) {
        int n = min(32, end - t);
        Edge e;
        e.s = 0; e.c = 0.0f;
        if (t + lane < end) e = g_csr[t + lane];
        for (int j = 0; j < n; j++) {
            int   s = __shfl_sync(0xFFFFFFFF, e.s, j);
            float c = __shfl_sync(0xFFFFFFFF, e.c, j);
            float4 v = xs4[s * 32 + lane];
            acc.x += c * v.x; acc.y += c * v.y;
            acc.z += c * v.z; acc.w += c * v.w;
        }
    }

    float di = g_dinv[node];
    float4 b = reinterpret_cast<const float4*>(b1)[lane];
    float4 r;
    r.x = fmaxf(di * acc.x + b.x, 0.0f);
    r.y = fmaxf(di * acc.y + b.y, 0.0f);
    r.z = fmaxf(di * acc.z + b.z, 0.0f);
    r.w = fmaxf(di * acc.w + b.w, 0.0f);
    reinterpret_cast<float4*>(g_h)[node * 32 + lane] = r;
}

__global__ void __launch_bounds__(256) k_agg2(const float* __restrict__ b2,
                                              float* __restrict__ out) {
    int node = (blockIdx.x * blockDim.x + threadIdx.x) >> 5;
    int lane = threadIdx.x & 31;
    if (node >= NN) return;

    const float2* hs2 = reinterpret_cast<const float2*>(g_hs);
    float2 acc = hs2[node * 32 + lane];  // self term

    int beg = g_rowptr[node], end = g_rowptr[node + 1];
    for (int t = beg; t < end; t += 32) {
        int n = min(32, end - t);
        Edge e;
        e.s = 0; e.c = 0.0f;
        if (t + lane < end) e = g_csr[t + lane];
        for (int j = 0; j < n; j++) {
            int   s = __shfl_sync(0xFFFFFFFF, e.s, j);
            float c = __shfl_sync(0xFFFFFFFF, e.c, j);
            float2 v = hs2[s * 32 + lane];
            acc.x += c * v.x; acc.y += c * v.y;
        }
    }

    float di = g_dinv[node];
    float2 b = reinterpret_cast<const float2*>(b2)[lane];
    float2 r;
    r.x = di * acc.x + b.x;
    r.y = di * acc.y + b.y;
    reinterpret_cast<float2*>(out)[node * 32 + lane] = r;
}

// ---------------------------------------------------------------------------
// launch
// ---------------------------------------------------------------------------
extern "C" void kernel_launch(void* const* d_in, const int* in_sizes, int n_in,
                              void* d_out, int out_size) {
    const float* x    = (const float*)d_in[0];
    const int*   ei32 = (const int*)d_in[1];
    const float* w    = (const float*)d_in[2];
    const float* W1   = (const float*)d_in[3];
    const float* b1   = (const float*)d_in[4];
    const float* W2   = (const float*)d_in[5];
    const float* b2   = (const float*)d_in[6];
    float* out = (float*)d_out;

    const int T = 256;

    // CSR build (graph shared by both layers)
    k_zero_detect<<<(NN + T - 1) / T, T>>>(ei32);
    k_count<<<(NE + T - 1) / T, T>>>(ei32);
    k_scan<<<1, 1024>>>();
    k_fill<<<(NE + T - 1) / T, T>>>(w);
    k_dinv<<<(NN * 32 + T - 1) / T, T>>>();

    // layer 1
    {
        dim3 grid((NN + 63) / 64, C_HID / 64);
        k_gemm1<<<grid, 256>>>(x, W1);
    }
    k_agg1<<<(NN * 32 + T - 1) / T, T>>>(b1);

    // layer 2
    {
        dim3 grid((NN + 63) / 64, C_OUT / 64);
        k_gemm2<<<grid, 256>>>(W2);
    }
    k_agg2<<<(NN * 32 + T - 1) / T, T>>>(b2, out);
}

// round 6
// speedup vs baseline: 3.0228x; 1.0945x over previous
#include <cuda_runtime.h>
#include <cuda_bf16.h>

constexpr int NN  = 10000;
constexpr int NE  = 640000;
constexpr int C_IN  = 128;
constexpr int C_HID = 128;
constexpr int C_OUT = 64;

struct __align__(8) Edge { int s; float c; };

// Scratch (device globals — no allocation allowed)
__device__ __align__(256) float g_dinv[NN];
__device__ __align__(256) int   g_count[NN];
__device__ __align__(256) int   g_rowptr[NN + 1];
__device__ __align__(256) int   g_sd  [NE];       // packed (s | d<<16)
__device__ __align__(256) int   g_rank[NE];
__device__ __align__(256) Edge  g_csr [NE];
__device__ __align__(256) float g_xs  [NN * C_HID];  // dinv * (x @ W1)
__device__ __align__(256) float g_h   [NN * C_HID];  // relu(layer1 out)
__device__ __align__(256) float g_hs  [NN * C_OUT];  // dinv * (h @ W2)

// edge_index dtype: 0 -> int64 (odd 32-bit words all zero), 1 -> int32.
__device__ int g_odd_nonzero;

__device__ __forceinline__ int load_idx(const int* __restrict__ ei32, long pos) {
    return (g_odd_nonzero == 0) ? ei32[2 * pos] : ei32[pos];
}

// ---------------------------------------------------------------------------
// zero counters + detect dtype
// ---------------------------------------------------------------------------
__global__ void k_zero_detect(const int* __restrict__ ei32) {
    int i = blockIdx.x * blockDim.x + threadIdx.x;
    if (i < NN) g_count[i] = 0;
    if (i < 2048) {
        if (ei32[2 * i + 1] != 0) atomicOr(&g_odd_nonzero, 1);
    }
}

// ---------------------------------------------------------------------------
// count + rank + pack (1 atomic per edge)
// ---------------------------------------------------------------------------
__global__ void k_count(const int* __restrict__ ei32) {
    int e = blockIdx.x * blockDim.x + threadIdx.x;
    if (e < NE) {
        int s = load_idx(ei32, e);
        int d = load_idx(ei32, (long)NE + e);
        s = min(max(s, 0), NN - 1);
        d = min(max(d, 0), NN - 1);
        g_sd[e] = s | (d << 16);
        g_rank[e] = atomicAdd(&g_count[d], 1);
    }
}

// single-block exclusive scan of g_count -> g_rowptr (1024 thr)
__global__ void k_scan() {
    constexpr int T = 1024, ITEMS = 10;
    __shared__ int partials[T];
    int t = threadIdx.x;
    int base = t * ITEMS;
    int local[ITEMS];
    int sum = 0;
#pragma unroll
    for (int i = 0; i < ITEMS; i++) {
        int idx = base + i;
        int v = (idx < NN) ? g_count[idx] : 0;
        local[i] = sum;
        sum += v;
    }
    partials[t] = sum;
    __syncthreads();
    for (int off = 1; off < T; off <<= 1) {
        int v = (t >= off) ? partials[t - off] : 0;
        __syncthreads();
        partials[t] += v;
        __syncthreads();
    }
    int prev = (t == 0) ? 0 : partials[t - 1];
#pragma unroll
    for (int i = 0; i < ITEMS; i++) {
        int idx = base + i;
        if (idx < NN) g_rowptr[idx] = prev + local[i];
    }
    if (t == T - 1) g_rowptr[NN] = partials[T - 1];
}

// fill CSR (no atomics)
__global__ void k_fill(const float* __restrict__ w) {
    int e = blockIdx.x * blockDim.x + threadIdx.x;
    if (e < NE) {
        int sd = g_sd[e];
        int s = sd & 0xFFFF;
        int d = sd >> 16;
        int pos = g_rowptr[d] + g_rank[e];
        Edge ed; ed.s = s; ed.c = w[e];
        g_csr[pos] = ed;
    }
}

// weighted degree per node from CSR rows; dinv = rsqrt(1 + sum w)
__global__ void k_dinv() {
    int gw = (blockIdx.x * blockDim.x + threadIdx.x) >> 5;
    int lane = threadIdx.x & 31;
    if (gw >= NN) return;
    int beg = g_rowptr[gw], end = g_rowptr[gw + 1];
    float sum = 0.0f;
    for (int i = beg + lane; i < end; i += 32) sum += g_csr[i].c;
#pragma unroll
    for (int off = 16; off > 0; off >>= 1)
        sum += __shfl_down_sync(0xFFFFFFFF, sum, off);
    if (lane == 0) g_dinv[gw] = rsqrtf(1.0f + sum);
}

// ---------------------------------------------------------------------------
// fp32 tiled GEMM, epilogue scales row by dinv[row]:  C = diag(dinv) * (A @ B)
// ---------------------------------------------------------------------------
__device__ __forceinline__ void gemm_body(const float* __restrict__ A,
                                          const float* __restrict__ B,
                                          float* __restrict__ C,
                                          int M, int N, int K) {
    constexpr int BM = 64, BN = 64, BK = 16;
    __shared__ float As[BK][BM];
    __shared__ float Bs[BK][BN];

    int rowBase = blockIdx.x * BM;
    int colBase = blockIdx.y * BN;
    int tx = threadIdx.x % 16;
    int ty = threadIdx.x / 16;

    float acc[4][4];
#pragma unroll
    for (int m = 0; m < 4; m++)
#pragma unroll
        for (int n = 0; n < 4; n++) acc[m][n] = 0.0f;

    for (int k0 = 0; k0 < K; k0 += BK) {
        for (int i = threadIdx.x; i < BM * BK; i += 256) {
            int r = i / BK, c = i % BK;
            int gr = rowBase + r;
            As[c][r] = (gr < M) ? A[(long)gr * K + k0 + c] : 0.0f;
        }
        for (int i = threadIdx.x; i < BK * BN; i += 256) {
            int r = i / BN, c = i % BN;
            Bs[r][c] = B[(long)(k0 + r) * N + colBase + c];
        }
        __syncthreads();

#pragma unroll
        for (int k = 0; k < BK; k++) {
            float a[4], b[4];
#pragma unroll
            for (int m = 0; m < 4; m++) a[m] = As[k][ty * 4 + m];
#pragma unroll
            for (int n = 0; n < 4; n++) b[n] = Bs[k][tx * 4 + n];
#pragma unroll
            for (int m = 0; m < 4; m++)
#pragma unroll
                for (int n = 0; n < 4; n++) acc[m][n] += a[m] * b[n];
        }
        __syncthreads();
    }

#pragma unroll
    for (int m = 0; m < 4; m++) {
        int gr = rowBase + ty * 4 + m;
        if (gr < M) {
            float di = g_dinv[gr];
#pragma unroll
            for (int n = 0; n < 4; n++)
                C[(long)gr * N + colBase + tx * 4 + n] = di * acc[m][n];
        }
    }
}

__global__ void k_gemm1(const float* __restrict__ x,
                        const float* __restrict__ W1) {
    gemm_body(x, W1, g_xs, NN, C_HID, C_IN);
}
__global__ void k_gemm2(const float* __restrict__ W2) {
    gemm_body(g_h, W2, g_hs, NN, C_OUT, C_HID);
}

// ---------------------------------------------------------------------------
// warp-per-node gather-aggregate; edges staged via smem (no shfl chain)
//   out[d,:] = relu( dinv[d] * ( xs[d,:] + sum_e w_e * xs[s_e,:] ) + b )
// ---------------------------------------------------------------------------
__global__ void __launch_bounds__(256) k_agg1(const float* __restrict__ b1) {
    __shared__ Edge tile[8][32];
    int wid  = threadIdx.x >> 5;
    int lane = threadIdx.x & 31;
    int node = blockIdx.x * 8 + wid;
    if (node >= NN) return;

    const float4* xs4 = reinterpret_cast<const float4*>(g_xs);
    float4 acc0 = xs4[node * 32 + lane];  // self term (already dinv-scaled)
    float4 acc1 = make_float4(0.f, 0.f, 0.f, 0.f);

    int beg = g_rowptr[node], end = g_rowptr[node + 1];
    for (int t = beg; t < end; t += 32) {
        int n = min(32, end - t);
        __syncwarp();
        if (t + lane < end) tile[wid][lane] = g_csr[t + lane];
        __syncwarp();
        if (n == 32) {
            for (int j = 0; j < 32; j += 4) {
                Edge e0 = tile[wid][j + 0];
                Edge e1 = tile[wid][j + 1];
                Edge e2 = tile[wid][j + 2];
                Edge e3 = tile[wid][j + 3];
                float4 v0 = xs4[e0.s * 32 + lane];
                float4 v1 = xs4[e1.s * 32 + lane];
                float4 v2 = xs4[e2.s * 32 + lane];
                float4 v3 = xs4[e3.s * 32 + lane];
                acc0.x += e0.c * v0.x; acc0.y += e0.c * v0.y;
                acc0.z += e0.c * v0.z; acc0.w += e0.c * v0.w;
                acc1.x += e1.c * v1.x; acc1.y += e1.c * v1.y;
                acc1.z += e1.c * v1.z; acc1.w += e1.c * v1.w;
                acc0.x += e2.c * v2.x; acc0.y += e2.c * v2.y;
                acc0.z += e2.c * v2.z; acc0.w += e2.c * v2.w;
                acc1.x += e3.c * v3.x; acc1.y += e3.c * v3.y;
                acc1.z += e3.c * v3.z; acc1.w += e3.c * v3.w;
            }
        } else {
            for (int j = 0; j < n; j++) {
                Edge e = tile[wid][j];
                float4 v = xs4[e.s * 32 + lane];
                acc0.x += e.c * v.x; acc0.y += e.c * v.y;
                acc0.z += e.c * v.z; acc0.w += e.c * v.w;
            }
        }
    }

    float di = g_dinv[node];
    float4 b = reinterpret_cast<const float4*>(b1)[lane];
    float4 r;
    r.x = fmaxf(di * (acc0.x + acc1.x) + b.x, 0.0f);
    r.y = fmaxf(di * (acc0.y + acc1.y) + b.y, 0.0f);
    r.z = fmaxf(di * (acc0.z + acc1.z) + b.z, 0.0f);
    r.w = fmaxf(di * (acc0.w + acc1.w) + b.w, 0.0f);
    reinterpret_cast<float4*>(g_h)[node * 32 + lane] = r;
}

__global__ void __launch_bounds__(256) k_agg2(const float* __restrict__ b2,
                                              float* __restrict__ out) {
    __shared__ Edge tile[8][32];
    int wid  = threadIdx.x >> 5;
    int lane = threadIdx.x & 31;
    int node = blockIdx.x * 8 + wid;
    if (node >= NN) return;

    const float2* hs2 = reinterpret_cast<const float2*>(g_hs);
    float2 acc0 = hs2[node * 32 + lane];  // self term
    float2 acc1 = make_float2(0.f, 0.f);

    int beg = g_rowptr[node], end = g_rowptr[node + 1];
    for (int t = beg; t < end; t += 32) {
        int n = min(32, end - t);
        __syncwarp();
        if (t + lane < end) tile[wid][lane] = g_csr[t + lane];
        __syncwarp();
        if (n == 32) {
            for (int j = 0; j < 32; j += 4) {
                Edge e0 = tile[wid][j + 0];
                Edge e1 = tile[wid][j + 1];
                Edge e2 = tile[wid][j + 2];
                Edge e3 = tile[wid][j + 3];
                float2 v0 = hs2[e0.s * 32 + lane];
                float2 v1 = hs2[e1.s * 32 + lane];
                float2 v2 = hs2[e2.s * 32 + lane];
                float2 v3 = hs2[e3.s * 32 + lane];
                acc0.x += e0.c * v0.x; acc0.y += e0.c * v0.y;
                acc1.x += e1.c * v1.x; acc1.y += e1.c * v1.y;
                acc0.x += e2.c * v2.x; acc0.y += e2.c * v2.y;
                acc1.x += e3.c * v3.x; acc1.y += e3.c * v3.y;
            }
        } else {
            for (int j = 0; j < n; j++) {
                Edge e = tile[wid][j];
                float2 v = hs2[e.s * 32 + lane];
                acc0.x += e.c * v.x; acc0.y += e.c * v.y;
            }
        }
    }

    float di = g_dinv[node];
    float2 b = reinterpret_cast<const float2*>(b2)[lane];
    float2 r;
    r.x = di * (acc0.x + acc1.x) + b.x;
    r.y = di * (acc0.y + acc1.y) + b.y;
    reinterpret_cast<float2*>(out)[node * 32 + lane] = r;
}

// ---------------------------------------------------------------------------
// launch
// ---------------------------------------------------------------------------
extern "C" void kernel_launch(void* const* d_in, const int* in_sizes, int n_in,
                              void* d_out, int out_size) {
    const float* x    = (const float*)d_in[0];
    const int*   ei32 = (const int*)d_in[1];
    const float* w    = (const float*)d_in[2];
    const float* W1   = (const float*)d_in[3];
    const float* b1   = (const float*)d_in[4];
    const float* W2   = (const float*)d_in[5];
    const float* b2   = (const float*)d_in[6];
    float* out = (float*)d_out;

    const int T = 256;

    // CSR build (graph shared by both layers)
    k_zero_detect<<<(NN + T - 1) / T, T>>>(ei32);
    k_count<<<(NE + T - 1) / T, T>>>(ei32);
    k_scan<<<1, 1024>>>();
    k_fill<<<(NE + T - 1) / T, T>>>(w);
    k_dinv<<<(NN * 32 + T - 1) / T, T>>>();

    // layer 1
    {
        dim3 grid((NN + 63) / 64, C_HID / 64);
        k_gemm1<<<grid, 256>>>(x, W1);
    }
    k_agg1<<<(NN + 7) / 8, 256>>>(b1);

    // layer 2
    {
        dim3 grid((NN + 63) / 64, C_OUT / 64);
        k_gemm2<<<grid, 256>>>(W2);
    }
    k_agg2<<<(NN + 7) / 8, 256>>>(b2, out);
}

// round 7
// speedup vs baseline: 3.2382x; 1.0713x over previous
#include <cuda_runtime.h>
#include <cuda_bf16.h>

constexpr int NN  = 10000;
constexpr int NE  = 640000;
constexpr int C_IN  = 128;
constexpr int C_HID = 128;
constexpr int C_OUT = 64;

struct __align__(8) Edge { int s; float c; };

// Scratch (device globals — no allocation allowed)
__device__ __align__(256) float g_dinv[NN];
__device__ __align__(256) int   g_count[NN];
__device__ __align__(256) int   g_rowptr[NN + 1];
__device__ __align__(256) int   g_sd  [NE];       // packed (s | d<<16)
__device__ __align__(256) int   g_rank[NE];
__device__ __align__(256) Edge  g_csr [NE];
__device__ __align__(256) float g_xw  [NN * C_HID];  // x @ W1 (unscaled)
__device__ __align__(256) float g_h   [NN * C_HID];  // relu(layer1 out)
__device__ __align__(256) float g_hw  [NN * C_OUT];  // h @ W2 (unscaled)

// edge_index dtype: 0 -> int64 (odd 32-bit words all zero), 1 -> int32.
__device__ int g_odd_nonzero;

__device__ __forceinline__ int load_idx(const int* __restrict__ ei32, long pos) {
    return (g_odd_nonzero == 0) ? ei32[2 * pos] : ei32[pos];
}

// ---------------------------------------------------------------------------
// zero counters + detect dtype
// ---------------------------------------------------------------------------
__global__ void k_zero_detect(const int* __restrict__ ei32) {
    int i = blockIdx.x * blockDim.x + threadIdx.x;
    if (i < NN) g_count[i] = 0;
    if (i < 2048) {
        if (ei32[2 * i + 1] != 0) atomicOr(&g_odd_nonzero, 1);
    }
}

// ---------------------------------------------------------------------------
// count + rank + pack (1 atomic per edge)
// ---------------------------------------------------------------------------
__global__ void k_count(const int* __restrict__ ei32) {
    int e = blockIdx.x * blockDim.x + threadIdx.x;
    if (e < NE) {
        int s = load_idx(ei32, e);
        int d = load_idx(ei32, (long)NE + e);
        s = min(max(s, 0), NN - 1);
        d = min(max(d, 0), NN - 1);
        g_sd[e] = s | (d << 16);
        g_rank[e] = atomicAdd(&g_count[d], 1);
    }
}

// single-block exclusive scan of g_count -> g_rowptr (1024 thr)
__global__ void k_scan() {
    constexpr int T = 1024, ITEMS = 10;
    __shared__ int partials[T];
    int t = threadIdx.x;
    int base = t * ITEMS;
    int local[ITEMS];
    int sum = 0;
#pragma unroll
    for (int i = 0; i < ITEMS; i++) {
        int idx = base + i;
        int v = (idx < NN) ? g_count[idx] : 0;
        local[i] = sum;
        sum += v;
    }
    partials[t] = sum;
    __syncthreads();
    for (int off = 1; off < T; off <<= 1) {
        int v = (t >= off) ? partials[t - off] : 0;
        __syncthreads();
        partials[t] += v;
        __syncthreads();
    }
    int prev = (t == 0) ? 0 : partials[t - 1];
#pragma unroll
    for (int i = 0; i < ITEMS; i++) {
        int idx = base + i;
        if (idx < NN) g_rowptr[idx] = prev + local[i];
    }
    if (t == T - 1) g_rowptr[NN] = partials[T - 1];
}

// fill CSR (no atomics)
__global__ void k_fill(const float* __restrict__ w) {
    int e = blockIdx.x * blockDim.x + threadIdx.x;
    if (e < NE) {
        int sd = g_sd[e];
        int s = sd & 0xFFFF;
        int d = sd >> 16;
        int pos = g_rowptr[d] + g_rank[e];
        Edge ed; ed.s = s; ed.c = w[e];
        g_csr[pos] = ed;
    }
}

// weighted degree per node from CSR rows; dinv = rsqrt(1 + sum w)
__global__ void k_dinv() {
    int gw = (blockIdx.x * blockDim.x + threadIdx.x) >> 5;
    int lane = threadIdx.x & 31;
    if (gw >= NN) return;
    int beg = g_rowptr[gw], end = g_rowptr[gw + 1];
    float sum = 0.0f;
    for (int i = beg + lane; i < end; i += 32) sum += g_csr[i].c;
#pragma unroll
    for (int off = 16; off > 0; off >>= 1)
        sum += __shfl_down_sync(0xFFFFFFFF, sum, off);
    if (lane == 0) g_dinv[gw] = rsqrtf(1.0f + sum);
}

// ---------------------------------------------------------------------------
// fp32 tiled GEMM (pure):  C = A @ B
// ---------------------------------------------------------------------------
__device__ __forceinline__ void gemm_body(const float* __restrict__ A,
                                          const float* __restrict__ B,
                                          float* __restrict__ C,
                                          int M, int N, int K) {
    constexpr int BM = 64, BN = 64, BK = 16;
    __shared__ float As[BK][BM];
    __shared__ float Bs[BK][BN];

    int rowBase = blockIdx.x * BM;
    int colBase = blockIdx.y * BN;
    int tx = threadIdx.x % 16;
    int ty = threadIdx.x / 16;

    float acc[4][4];
#pragma unroll
    for (int m = 0; m < 4; m++)
#pragma unroll
        for (int n = 0; n < 4; n++) acc[m][n] = 0.0f;

    for (int k0 = 0; k0 < K; k0 += BK) {
        for (int i = threadIdx.x; i < BM * BK; i += 256) {
            int r = i / BK, c = i % BK;
            int gr = rowBase + r;
            As[c][r] = (gr < M) ? A[(long)gr * K + k0 + c] : 0.0f;
        }
        for (int i = threadIdx.x; i < BK * BN; i += 256) {
            int r = i / BN, c = i % BN;
            Bs[r][c] = B[(long)(k0 + r) * N + colBase + c];
        }
        __syncthreads();

#pragma unroll
        for (int k = 0; k < BK; k++) {
            float a[4], b[4];
#pragma unroll
            for (int m = 0; m < 4; m++) a[m] = As[k][ty * 4 + m];
#pragma unroll
            for (int n = 0; n < 4; n++) b[n] = Bs[k][tx * 4 + n];
#pragma unroll
            for (int m = 0; m < 4; m++)
#pragma unroll
                for (int n = 0; n < 4; n++) acc[m][n] += a[m] * b[n];
        }
        __syncthreads();
    }

#pragma unroll
    for (int m = 0; m < 4; m++) {
        int gr = rowBase + ty * 4 + m;
        if (gr < M) {
#pragma unroll
            for (int n = 0; n < 4; n++)
                C[(long)gr * N + colBase + tx * 4 + n] = acc[m][n];
        }
    }
}

__global__ void k_gemm1(const float* __restrict__ x,
                        const float* __restrict__ W1) {
    gemm_body(x, W1, g_xw, NN, C_HID, C_IN);
}
__global__ void k_gemm2(const float* __restrict__ W2) {
    gemm_body(g_h, W2, g_hw, NN, C_OUT, C_HID);
}

// ---------------------------------------------------------------------------
// warp-per-node gather-aggregate; dinv applied at staging + epilogue
//   out[d,:] = relu( dinv[d]*( dinv[d]*xw[d,:] + sum_e (w_e*dinv[s])*xw[s,:] ) + b )
// ---------------------------------------------------------------------------
__global__ void __launch_bounds__(256) k_agg1(const float* __restrict__ b1) {
    __shared__ Edge tile[8][32];
    int wid  = threadIdx.x >> 5;
    int lane = threadIdx.x & 31;
    int node = blockIdx.x * 8 + wid;
    if (node >= NN) return;

    const float4* xw4 = reinterpret_cast<const float4*>(g_xw);
    float di = g_dinv[node];
    float4 self = xw4[node * 32 + lane];
    float4 acc0 = make_float4(di * self.x, di * self.y, di * self.z, di * self.w);
    float4 acc1 = make_float4(0.f, 0.f, 0.f, 0.f);

    int beg = g_rowptr[node], end = g_rowptr[node + 1];
    for (int t = beg; t < end; t += 32) {
        int n = min(32, end - t);
        Edge e;
        if (t + lane < end) {
            e = g_csr[t + lane];
            e.c *= g_dinv[e.s];
        }
        __syncwarp();
        if (t + lane < end) tile[wid][lane] = e;
        __syncwarp();
        if (n == 32) {
            for (int j = 0; j < 32; j += 4) {
                Edge e0 = tile[wid][j + 0];
                Edge e1 = tile[wid][j + 1];
                Edge e2 = tile[wid][j + 2];
                Edge e3 = tile[wid][j + 3];
                float4 v0 = xw4[e0.s * 32 + lane];
                float4 v1 = xw4[e1.s * 32 + lane];
                float4 v2 = xw4[e2.s * 32 + lane];
                float4 v3 = xw4[e3.s * 32 + lane];
                acc0.x += e0.c * v0.x; acc0.y += e0.c * v0.y;
                acc0.z += e0.c * v0.z; acc0.w += e0.c * v0.w;
                acc1.x += e1.c * v1.x; acc1.y += e1.c * v1.y;
                acc1.z += e1.c * v1.z; acc1.w += e1.c * v1.w;
                acc0.x += e2.c * v2.x; acc0.y += e2.c * v2.y;
                acc0.z += e2.c * v2.z; acc0.w += e2.c * v2.w;
                acc1.x += e3.c * v3.x; acc1.y += e3.c * v3.y;
                acc1.z += e3.c * v3.z; acc1.w += e3.c * v3.w;
            }
        } else {
            for (int j = 0; j < n; j++) {
                Edge e0 = tile[wid][j];
                float4 v = xw4[e0.s * 32 + lane];
                acc0.x += e0.c * v.x; acc0.y += e0.c * v.y;
                acc0.z += e0.c * v.z; acc0.w += e0.c * v.w;
            }
        }
    }

    float4 b = reinterpret_cast<const float4*>(b1)[lane];
    float4 r;
    r.x = fmaxf(di * (acc0.x + acc1.x) + b.x, 0.0f);
    r.y = fmaxf(di * (acc0.y + acc1.y) + b.y, 0.0f);
    r.z = fmaxf(di * (acc0.z + acc1.z) + b.z, 0.0f);
    r.w = fmaxf(di * (acc0.w + acc1.w) + b.w, 0.0f);
    reinterpret_cast<float4*>(g_h)[node * 32 + lane] = r;
}

__global__ void __launch_bounds__(256) k_agg2(const float* __restrict__ b2,
                                              float* __restrict__ out) {
    __shared__ Edge tile[8][32];
    int wid  = threadIdx.x >> 5;
    int lane = threadIdx.x & 31;
    int node = blockIdx.x * 8 + wid;
    if (node >= NN) return;

    const float2* hw2 = reinterpret_cast<const float2*>(g_hw);
    float di = g_dinv[node];
    float2 self = hw2[node * 32 + lane];
    float2 acc0 = make_float2(di * self.x, di * self.y);
    float2 acc1 = make_float2(0.f, 0.f);

    int beg = g_rowptr[node], end = g_rowptr[node + 1];
    for (int t = beg; t < end; t += 32) {
        int n = min(32, end - t);
        Edge e;
        if (t + lane < end) {
            e = g_csr[t + lane];
            e.c *= g_dinv[e.s];
        }
        __syncwarp();
        if (t + lane < end) tile[wid][lane] = e;
        __syncwarp();
        if (n == 32) {
            for (int j = 0; j < 32; j += 4) {
                Edge e0 = tile[wid][j + 0];
                Edge e1 = tile[wid][j + 1];
                Edge e2 = tile[wid][j + 2];
                Edge e3 = tile[wid][j + 3];
                float2 v0 = hw2[e0.s * 32 + lane];
                float2 v1 = hw2[e1.s * 32 + lane];
                float2 v2 = hw2[e2.s * 32 + lane];
                float2 v3 = hw2[e3.s * 32 + lane];
                acc0.x += e0.c * v0.x; acc0.y += e0.c * v0.y;
                acc1.x += e1.c * v1.x; acc1.y += e1.c * v1.y;
                acc0.x += e2.c * v2.x; acc0.y += e2.c * v2.y;
                acc1.x += e3.c * v3.x; acc1.y += e3.c * v3.y;
            }
        } else {
            for (int j = 0; j < n; j++) {
                Edge e0 = tile[wid][j];
                float2 v = hw2[e0.s * 32 + lane];
                acc0.x += e0.c * v.x; acc0.y += e0.c * v.y;
            }
        }
    }

    float2 b = reinterpret_cast<const float2*>(b2)[lane];
    float2 r;
    r.x = di * (acc0.x + acc1.x) + b.x;
    r.y = di * (acc0.y + acc1.y) + b.y;
    reinterpret_cast<float2*>(out)[node * 32 + lane] = r;
}

// ---------------------------------------------------------------------------
// launch (CSR build on default stream, GEMM1 forked to a side stream)
// ---------------------------------------------------------------------------
extern "C" void kernel_launch(void* const* d_in, const int* in_sizes, int n_in,
                              void* d_out, int out_size) {
    const float* x    = (const float*)d_in[0];
    const int*   ei32 = (const int*)d_in[1];
    const float* w    = (const float*)d_in[2];
    const float* W1   = (const float*)d_in[3];
    const float* b1   = (const float*)d_in[4];
    const float* W2   = (const float*)d_in[5];
    const float* b2   = (const float*)d_in[6];
    float* out = (float*)d_out;

    // created once on the (uncaptured) correctness call; reused under capture
    static cudaStream_t s1 = nullptr;
    static cudaEvent_t evFork = nullptr, evJoin = nullptr;
    if (s1 == nullptr) {
        cudaStreamCreateWithFlags(&s1, cudaStreamNonBlocking);
        cudaEventCreateWithFlags(&evFork, cudaEventDisableTiming);
        cudaEventCreateWithFlags(&evJoin, cudaEventDisableTiming);
    }

    const int T = 256;

    // fork: GEMM1 is independent of the graph pipeline
    cudaEventRecord(evFork, 0);
    cudaStreamWaitEvent(s1, evFork, 0);
    {
        dim3 grid((NN + 63) / 64, C_HID / 64);
        k_gemm1<<<grid, 256, 0, s1>>>(x, W1);
    }
    cudaEventRecord(evJoin, s1);

    // CSR build (default stream)
    k_zero_detect<<<(NN + T - 1) / T, T>>>(ei32);
    k_count<<<(NE + T - 1) / T, T>>>(ei32);
    k_scan<<<1, 1024>>>();
    k_fill<<<(NE + T - 1) / T, T>>>(w);
    k_dinv<<<(NN * 32 + T - 1) / T, T>>>();

    // join: aggregation needs both CSR and xw
    cudaStreamWaitEvent(0, evJoin, 0);

    k_agg1<<<(NN + 7) / 8, 256>>>(b1);
    {
        dim3 grid((NN + 63) / 64, C_OUT / 64);
        k_gemm2<<<grid, 256>>>(W2);
    }
    k_agg2<<<(NN + 7) / 8, 256>>>(b2, out);
}